// round 7
// baseline (speedup 1.0000x reference)
#include <cuda_runtime.h>
#include <cstdint>

#define NROWS 8192
#define DDIM  128
#define NCLS  1000
#define KSPLIT 2
#define KRANGE (NROWS/KSPLIT)   // 4096
#define KCH   32
#define NCHUNK (KRANGE/KCH)     // 128
#define APAD  36                // floats per smem row (32 + 4 pad)
#define TILE_B (128*APAD*4)     // 18432 bytes per tile buffer

// dyn smem layout (bytes from base):
//  A0:0  A1:18432  B0:36864  B1:55296  sqk:73728(16384B)  sqm:90112(512B)
#define OFF_A0 0
#define OFF_B0 36864
#define OFF_SQK 73728
#define OFF_SQM 90112
#define DYN_BYTES (90112 + 512)

__device__ __align__(16) float g_XT[(size_t)DDIM*NROWS];  // tf32-rounded X^T [d][j]
__device__ float  g_sq[NROWS];
__device__ double g_acc[3];   // 0: ce-sum  1: T  2: cross

// ---------------- helpers ----------------
__device__ __forceinline__ uint32_t smem_u32(const void* p){
    uint32_t a;
    asm("{ .reg .u64 t; cvta.to.shared.u64 t, %1; cvt.u32.u64 %0, t; }" : "=r"(a) : "l"(p));
    return a;
}
__device__ __forceinline__ uint32_t f2tf32(float x){
    uint32_t u;
    asm("cvt.rna.tf32.f32 %0, %1;" : "=r"(u) : "f"(x));
    return u;
}
__device__ __forceinline__ uint32_t lds32(uint32_t a){
    uint32_t v;
    asm("ld.shared.b32 %0, [%1];" : "=r"(v) : "r"(a));
    return v;
}
__device__ __forceinline__ void sts128(uint32_t a, uint32_t x, uint32_t y, uint32_t z, uint32_t w){
    asm volatile("st.shared.v4.b32 [%0], {%1,%2,%3,%4};" :: "r"(a), "r"(x), "r"(y), "r"(z), "r"(w));
}
__device__ __forceinline__ void cp16(uint32_t dst, const void* src){
    asm volatile("cp.async.cg.shared.global [%0], [%1], 16;" :: "r"(dst), "l"(src));
}
__device__ __forceinline__ void mma_tf32(float* c, const uint32_t* a, const uint32_t* b){
    asm volatile(
        "mma.sync.aligned.m16n8k8.row.col.f32.tf32.tf32.f32 "
        "{%0,%1,%2,%3}, {%4,%5,%6,%7}, {%8,%9}, {%0,%1,%2,%3};"
        : "+f"(c[0]), "+f"(c[1]), "+f"(c[2]), "+f"(c[3])
        : "r"(a[0]), "r"(a[1]), "r"(a[2]), "r"(a[3]), "r"(b[0]), "r"(b[1]));
}

// ---------------- kernels ----------------
__global__ void k_zero(){ if (threadIdx.x < 3) g_acc[threadIdx.x] = 0.0; }

// sq[j] = ||x_j||^2 (exact fp32), XT[d][j] = tf32_round(X[j][d])
__global__ void __launch_bounds__(256) k_prep(const float* __restrict__ X){
    __shared__ float tile[64*129];
    int tid = threadIdx.x;
    int j0 = blockIdx.x * 64;
#pragma unroll
    for (int p = 0; p < 8; ++p){
        int idx = p*256 + tid;        // float4 units
        int r = idx >> 5;
        int c = idx & 31;
        float4 v = ((const float4*)(X + (size_t)(j0 + r)*DDIM))[c];
        tile[r*129 + c*4 + 0] = v.x;
        tile[r*129 + c*4 + 1] = v.y;
        tile[r*129 + c*4 + 2] = v.z;
        tile[r*129 + c*4 + 3] = v.w;
    }
    __syncthreads();
    if (tid < 64){
        float s = 0.f;
        const float* row = tile + tid*129;
#pragma unroll 8
        for (int c = 0; c < 128; ++c) s += row[c]*row[c];
        g_sq[j0 + tid] = s;
    }
#pragma unroll
    for (int p = 0; p < 8; ++p){
        int u  = p*256 + tid;         // 0..2047
        int d  = u >> 4;              // 0..127
        int ju = (u & 15) * 4;        // group of 4 j's
        uint4 o;
        o.x = f2tf32(tile[(ju+0)*129 + d]);
        o.y = f2tf32(tile[(ju+1)*129 + d]);
        o.z = f2tf32(tile[(ju+2)*129 + d]);
        o.w = f2tf32(tile[(ju+3)*129 + d]);
        *(uint4*)(g_XT + (size_t)d*NROWS + j0 + ju) = o;
    }
}

__global__ void __launch_bounds__(256) k_ce(const float* __restrict__ preds,
                                            const int* __restrict__ tgt){
    __shared__ float red[8];
    int tid = threadIdx.x, wid = tid>>5, lane = tid&31;
    int r = blockIdx.x*8 + wid;
    const float* row = preds + (size_t)r*NCLS;
    float m = -3.4e38f;
    for (int c = lane; c < NCLS; c += 32) m = fmaxf(m, row[c]);
#pragma unroll
    for (int o = 16; o; o >>= 1) m = fmaxf(m, __shfl_xor_sync(~0u, m, o));
    float s = 0.f;
    for (int c = lane; c < NCLS; c += 32) s += __expf(row[c] - m);
#pragma unroll
    for (int o = 16; o; o >>= 1) s += __shfl_xor_sync(~0u, s, o);
    if (lane == 0){
        int t = tgt[r];
        red[wid] = -(row[t] - m - __logf(s));
    }
    __syncthreads();
    if (tid == 0){
        float b = 0.f;
#pragma unroll
        for (int w = 0; w < 8; ++w) b += red[w];
        atomicAdd(&g_acc[0], (double)b);
    }
}

__global__ void __launch_bounds__(256, 1)
k_main(const float* __restrict__ L, const float* __restrict__ X){
    extern __shared__ __align__(16) char dyn[];
    __shared__ float s_red[16];
    uint32_t base = smem_u32(dyn);
    float* sqk = (float*)(dyn + OFF_SQK);
    float* sqm = (float*)(dyn + OFF_SQM);

    int tid = threadIdx.x, wid = tid>>5, lane = tid&31;
    int m0 = (blockIdx.x >> 1) * 128;
    int k0base = (blockIdx.x & 1) * KRANGE;

    // preload sq slabs
    for (int i = tid; i < KRANGE/4; i += 256)
        ((float4*)sqk)[i] = ((const float4*)(g_sq + k0base))[i];
    if (tid < 32) ((float4*)sqm)[tid] = ((const float4*)(g_sq + m0))[tid];
    __syncthreads();

    // loader mapping: row = tid>>1 (0..127), half = tid&1 (16-float halves)
    int lrow = tid >> 1, lhalf = tid & 1;
    const float4* Lp4 = (const float4*)(L + (size_t)(m0 + lrow)*NROWS + k0base + lhalf*16);
    const float*  Bp  = g_XT + (size_t)lrow*NROWS + k0base + lhalf*16;
    float my_sqm = sqm[lrow];
    uint32_t stsA_base = base + (lrow*APAD + lhalf*16)*4;
    uint32_t stsB_base = base + OFF_B0 + (lrow*APAD + lhalf*16)*4;

    // warp tiling: 2 (M) x 4 (N) warps; warp tile 64x32
    int warp_m = wid >> 2, warp_n = wid & 3;
    int r = lane >> 2, cg = lane & 3;
    uint32_t aA = base + ((warp_m*64 + r)*APAD + cg)*4;
    uint32_t aB = base + OFF_B0 + ((warp_n*32 + r)*APAD + cg)*4;

    float acc[4][4][4];
#pragma unroll
    for (int i = 0; i < 4; ++i)
#pragma unroll
        for (int j = 0; j < 4; ++j)
#pragma unroll
            for (int q = 0; q < 4; ++q) acc[i][j][q] = 0.f;

    float tloc = 0.f;
    float4 av[4];

    // prologue: stage chunk 0
#pragma unroll
    for (int q = 0; q < 4; ++q) av[q] = Lp4[q];
#pragma unroll
    for (int q = 0; q < 4; ++q) cp16(stsB_base + q*16, Bp + 4*q);
    asm volatile("cp.async.commit_group;" ::: "memory");

#pragma unroll 1
    for (int c = 0; c < NCHUNK; ++c){
        uint32_t abufA = stsA_base + (c&1)*TILE_B;
        // STS A(c): fused T term + tf32 convert
        int jb = c*KCH + lhalf*16;
#pragma unroll
        for (int q = 0; q < 4; ++q){
            float4 v = av[q];
            const float* s4 = sqk + jb + 4*q;
            tloc += (v.x+v.y+v.z+v.w)*my_sqm
                  + v.x*s4[0] + v.y*s4[1] + v.z*s4[2] + v.w*s4[3];
            sts128(abufA + q*16, f2tf32(v.x), f2tf32(v.y), f2tf32(v.z), f2tf32(v.w));
        }
        asm volatile("cp.async.wait_group 0;" ::: "memory");
        __syncthreads();

        // stage chunk c+1
        if (c + 1 < NCHUNK){
            int kn = (c+1)*KCH;
#pragma unroll
            for (int q = 0; q < 4; ++q) av[q] = Lp4[(kn>>2) + q];
            uint32_t bdst = stsB_base + ((c+1)&1)*TILE_B;
#pragma unroll
            for (int q = 0; q < 4; ++q) cp16(bdst + q*16, Bp + kn + 4*q);
        }
        asm volatile("cp.async.commit_group;" ::: "memory");

        // MMA over buffer c
        uint32_t bA = aA + (c&1)*TILE_B;
        uint32_t bB = aB + (c&1)*TILE_B;
#pragma unroll
        for (int k8 = 0; k8 < KCH; k8 += 8){
            uint32_t af[4][4], bf[4][2];
#pragma unroll
            for (int tm = 0; tm < 4; ++tm){
                uint32_t p = bA + (tm*16*APAD + k8)*4;
                af[tm][0] = lds32(p);
                af[tm][1] = lds32(p + 8*APAD*4);
                af[tm][2] = lds32(p + 16);
                af[tm][3] = lds32(p + 8*APAD*4 + 16);
            }
#pragma unroll
            for (int tn = 0; tn < 4; ++tn){
                uint32_t p = bB + (tn*8*APAD + k8)*4;
                bf[tn][0] = lds32(p);
                bf[tn][1] = lds32(p + 16);
            }
#pragma unroll
            for (int tm = 0; tm < 4; ++tm)
#pragma unroll
                for (int tn = 0; tn < 4; ++tn)
                    mma_tf32(acc[tm][tn], af[tm], bf[tn]);
        }
    }

    // epilogue: cross += acc .* X (exact fp32)
    float cpart = 0.f;
#pragma unroll
    for (int tm = 0; tm < 4; ++tm){
#pragma unroll
        for (int tn = 0; tn < 4; ++tn){
#pragma unroll
            for (int q = 0; q < 4; ++q){
                int mrow = m0 + warp_m*64 + tm*16 + r + ((q>>1)<<3);
                int ncol = warp_n*32 + tn*8 + cg*2 + (q&1);
                cpart += acc[tm][tn][q] * __ldg(X + (size_t)mrow*DDIM + ncol);
            }
        }
    }

#pragma unroll
    for (int o = 16; o; o >>= 1){
        tloc  += __shfl_xor_sync(~0u, tloc,  o);
        cpart += __shfl_xor_sync(~0u, cpart, o);
    }
    if (lane == 0){ s_red[wid] = tloc; s_red[8 + wid] = cpart; }
    __syncthreads();
    if (tid == 0){
        float ts = 0.f, cs = 0.f;
#pragma unroll
        for (int w = 0; w < 8; ++w){ ts += s_red[w]; cs += s_red[8 + w]; }
        atomicAdd(&g_acc[1], (double)ts);
        atomicAdd(&g_acc[2], (double)cs);
    }
}

__global__ void k_final(float* out, int n){
    double v = g_acc[0] / (double)NROWS + 0.1 * (g_acc[1] - 2.0 * g_acc[2]);
    for (int i = threadIdx.x; i < n; i += blockDim.x) out[i] = (float)v;
}

extern "C" void kernel_launch(void* const* d_in, const int* in_sizes, int n_in,
                              void* d_out, int out_size){
    const float* preds = (const float*)d_in[0];
    const int*   tgt   = (const int*)d_in[1];
    const float* L     = (const float*)d_in[2];
    const float* X     = (const float*)d_in[3];
    float* out = (float*)d_out;
    (void)in_sizes; (void)n_in;

    cudaFuncSetAttribute((const void*)k_main, cudaFuncAttributeMaxDynamicSharedMemorySize, DYN_BYTES);

    k_zero<<<1, 32>>>();
    k_prep<<<NROWS/64, 256>>>(X);
    k_ce<<<NROWS/8, 256>>>(preds, tgt);
    k_main<<<(NROWS/128)*KSPLIT, 256, DYN_BYTES>>>(L, X);
    k_final<<<1, 256>>>(out, out_size);
}

// round 8
// speedup vs baseline: 1.1429x; 1.1429x over previous
#include <cuda_runtime.h>
#include <cstdint>

#define NROWS 8192
#define DDIM  128
#define NCLS  1000
#define KRANGE 4096            // split-K 2
#define KCH   32
#define NCHUNK (KRANGE/KCH)    // 128
#define NSTAGE 4
#define APAD  36               // floats per smem row (32 + 4 pad) -> conflict-free frags
#define TILE_B (128*APAD*4)    // 18432 B per stage per operand
#define OFF_B   (NSTAGE*TILE_B)      // 73728
#define OFF_SQK (2*NSTAGE*TILE_B)    // 147456
#define DYN_BYTES (OFF_SQK + KRANGE*4)  // 163840

__device__ __align__(16) float g_XT[(size_t)DDIM*NROWS];  // tf32-rounded X^T [d][j]
__device__ float  g_sq[NROWS];
__device__ double g_acc[3];   // 0: ce-sum  1: T  2: cross

// ---------------- helpers ----------------
__device__ __forceinline__ uint32_t smem_u32(const void* p){
    uint32_t a;
    asm("{ .reg .u64 t; cvta.to.shared.u64 t, %1; cvt.u32.u64 %0, t; }" : "=r"(a) : "l"(p));
    return a;
}
__device__ __forceinline__ uint32_t f2tf32(float x){
    uint32_t u;
    asm("cvt.rna.tf32.f32 %0, %1;" : "=r"(u) : "f"(x));
    return u;
}
__device__ __forceinline__ uint32_t lds32(uint32_t a){
    uint32_t v;
    asm("ld.shared.b32 %0, [%1];" : "=r"(v) : "r"(a));
    return v;
}
__device__ __forceinline__ float4 lds128f(uint32_t a){
    float4 v;
    asm volatile("ld.shared.v4.f32 {%0,%1,%2,%3}, [%4];"
                 : "=f"(v.x), "=f"(v.y), "=f"(v.z), "=f"(v.w) : "r"(a));
    return v;
}
__device__ __forceinline__ void cp16(uint32_t dst, const void* src){
    asm volatile("cp.async.cg.shared.global [%0], [%1], 16;" :: "r"(dst), "l"(src));
}
__device__ __forceinline__ void mma_tf32(float* c, const uint32_t* a, const uint32_t* b){
    asm volatile(
        "mma.sync.aligned.m16n8k8.row.col.f32.tf32.tf32.f32 "
        "{%0,%1,%2,%3}, {%4,%5,%6,%7}, {%8,%9}, {%0,%1,%2,%3};"
        : "+f"(c[0]), "+f"(c[1]), "+f"(c[2]), "+f"(c[3])
        : "r"(a[0]), "r"(a[1]), "r"(a[2]), "r"(a[3]), "r"(b[0]), "r"(b[1]));
}

// ---------------- prep: zero acc, sq[j] exact, XT tf32 ----------------
__global__ void __launch_bounds__(256) k_prep(const float* __restrict__ X){
    __shared__ float tile[64*129];
    int tid = threadIdx.x;
    int j0 = blockIdx.x * 64;
    if (blockIdx.x == 0 && tid < 3) g_acc[tid] = 0.0;
#pragma unroll
    for (int p = 0; p < 8; ++p){
        int idx = p*256 + tid;
        int r = idx >> 5;
        int c = idx & 31;
        float4 v = ((const float4*)(X + (size_t)(j0 + r)*DDIM))[c];
        tile[r*129 + c*4 + 0] = v.x;
        tile[r*129 + c*4 + 1] = v.y;
        tile[r*129 + c*4 + 2] = v.z;
        tile[r*129 + c*4 + 3] = v.w;
    }
    __syncthreads();
    if (tid < 64){
        float s = 0.f;
        const float* row = tile + tid*129;
#pragma unroll 8
        for (int c = 0; c < 128; ++c) s += row[c]*row[c];
        g_sq[j0 + tid] = s;
    }
#pragma unroll
    for (int p = 0; p < 8; ++p){
        int u  = p*256 + tid;
        int d  = u >> 4;
        int ju = (u & 15) * 4;
        uint4 o;
        o.x = f2tf32(tile[(ju+0)*129 + d]);
        o.y = f2tf32(tile[(ju+1)*129 + d]);
        o.z = f2tf32(tile[(ju+2)*129 + d]);
        o.w = f2tf32(tile[(ju+3)*129 + d]);
        *(uint4*)(g_XT + (size_t)d*NROWS + j0 + ju) = o;
    }
}

// ---------------- main: GEMM blocks 0..127, CE blocks 128..147 ----------------
__global__ void __launch_bounds__(256, 1)
k_main(const float* __restrict__ L, const float* __restrict__ X,
       const float* __restrict__ preds, const int* __restrict__ tgt){
    extern __shared__ __align__(16) char dyn[];
    __shared__ float s_red[16];
    int tid = threadIdx.x, wid = tid>>5, lane = tid&31;

    if (blockIdx.x >= 128){
        // ---- cross-entropy: 20 CTAs x 8 warps, 1 warp per row ----
        int g = (blockIdx.x - 128)*8 + wid;     // 0..159
        float ce = 0.f;
        for (int r = g; r < NROWS; r += 160){
            const float4* row4 = (const float4*)(preds + (size_t)r*NCLS);
            float s = 0.f;
            for (int c4 = lane; c4 < NCLS/4; c4 += 32){
                float4 v = __ldg(row4 + c4);
                s += __expf(v.x) + __expf(v.y) + __expf(v.z) + __expf(v.w);
            }
#pragma unroll
            for (int o = 16; o; o >>= 1) s += __shfl_xor_sync(~0u, s, o);
            if (lane == 0)
                ce += __logf(s) - __ldg(preds + (size_t)r*NCLS + __ldg(tgt + r));
        }
        if (lane == 0) atomicAdd(&g_acc[0], (double)ce);
        return;
    }

    // ---- GEMM + fused T ----
    uint32_t base = smem_u32(dyn);
    float* sqk = (float*)(dyn + OFF_SQK);
    int m0 = (blockIdx.x >> 1) * 128;
    int k0 = (blockIdx.x & 1) * KRANGE;

    for (int i = tid; i < KRANGE/4; i += 256)
        ((float4*)sqk)[i] = ((const float4*)(g_sq + k0))[i];

    int lrow = tid >> 1, lhalf = tid & 1;
    const float* Ap = L    + (size_t)(m0 + lrow)*NROWS + k0 + lhalf*16;
    const float* Bp = g_XT + (size_t)lrow*NROWS       + k0 + lhalf*16;
    float my_sqm = __ldg(g_sq + m0 + lrow);
    uint32_t aoff = (uint32_t)(lrow*APAD + lhalf*16)*4;

    __syncthreads();

    // prologue: stages 0..NSTAGE-2
#pragma unroll
    for (int s = 0; s < NSTAGE-1; ++s){
        uint32_t da = base + s*TILE_B + aoff;
        uint32_t db = da + OFF_B;
#pragma unroll
        for (int q = 0; q < 4; ++q){
            cp16(da + q*16, Ap + s*KCH + q*4);
            cp16(db + q*16, Bp + s*KCH + q*4);
        }
        asm volatile("cp.async.commit_group;" ::: "memory");
    }

    int warp_m = wid >> 2, warp_n = wid & 3;
    int r = lane >> 2, cg = lane & 3;
    uint32_t aA = base + (uint32_t)((warp_m*64 + r)*APAD + cg)*4;
    uint32_t aB = base + OFF_B + (uint32_t)((warp_n*32 + r)*APAD + cg)*4;

    float acc[4][4][4];
#pragma unroll
    for (int i = 0; i < 4; ++i)
#pragma unroll
        for (int j = 0; j < 4; ++j)
#pragma unroll
            for (int q = 0; q < 4; ++q) acc[i][j][q] = 0.f;
    float tloc = 0.f;

#pragma unroll 1
    for (int c = 0; c < NCHUNK; ++c){
        asm volatile("cp.async.wait_group 2;" ::: "memory");
        __syncthreads();

        // stage c+NSTAGE-1 (overwrites buf (c-1)%NSTAGE — consumed by all before this barrier)
        int cn = c + NSTAGE - 1;
        if (cn < NCHUNK){
            uint32_t da = base + (cn & (NSTAGE-1))*TILE_B + aoff;
            uint32_t db = da + OFF_B;
#pragma unroll
            for (int q = 0; q < 4; ++q){
                cp16(da + q*16, Ap + cn*KCH + q*4);
                cp16(db + q*16, Bp + cn*KCH + q*4);
            }
        }
        asm volatile("cp.async.commit_group;" ::: "memory");

        int buf = c & (NSTAGE-1);

        // fused T: read back this thread's raw L values from smem
        {
            uint32_t ta = base + buf*TILE_B + aoff;
            const float* sk = sqk + c*KCH + lhalf*16;
#pragma unroll
            for (int q = 0; q < 4; ++q){
                float4 v = lds128f(ta + q*16);
                tloc += (v.x+v.y+v.z+v.w)*my_sqm
                      + v.x*sk[q*4+0] + v.y*sk[q*4+1] + v.z*sk[q*4+2] + v.w*sk[q*4+3];
            }
        }

        // MMA over buffer c (A = raw fp32 bits, HW truncates to tf32)
        uint32_t bA = aA + buf*TILE_B;
        uint32_t bB = aB + buf*TILE_B;
#pragma unroll
        for (int k8 = 0; k8 < KCH; k8 += 8){
            uint32_t af[4][4], bf[4][2];
#pragma unroll
            for (int tm = 0; tm < 4; ++tm){
                uint32_t p = bA + (uint32_t)(tm*16*APAD + k8)*4;
                af[tm][0] = lds32(p);
                af[tm][1] = lds32(p + 8*APAD*4);
                af[tm][2] = lds32(p + 16);
                af[tm][3] = lds32(p + 8*APAD*4 + 16);
            }
#pragma unroll
            for (int tn = 0; tn < 4; ++tn){
                uint32_t p = bB + (uint32_t)(tn*8*APAD + k8)*4;
                bf[tn][0] = lds32(p);
                bf[tn][1] = lds32(p + 16);
            }
#pragma unroll
            for (int tm = 0; tm < 4; ++tm)
#pragma unroll
                for (int tn = 0; tn < 4; ++tn)
                    mma_tf32(acc[tm][tn], af[tm], bf[tn]);
        }
    }

    // epilogue: cross += acc .* X (exact fp32)
    float cpart = 0.f;
#pragma unroll
    for (int tm = 0; tm < 4; ++tm){
#pragma unroll
        for (int tn = 0; tn < 4; ++tn){
#pragma unroll
            for (int q = 0; q < 4; ++q){
                int mrow = m0 + warp_m*64 + tm*16 + r + ((q>>1)<<3);
                int ncol = warp_n*32 + tn*8 + cg*2 + (q&1);
                cpart += acc[tm][tn][q] * __ldg(X + (size_t)mrow*DDIM + ncol);
            }
        }
    }

#pragma unroll
    for (int o = 16; o; o >>= 1){
        tloc  += __shfl_xor_sync(~0u, tloc,  o);
        cpart += __shfl_xor_sync(~0u, cpart, o);
    }
    if (lane == 0){ s_red[wid] = tloc; s_red[8 + wid] = cpart; }
    __syncthreads();
    if (tid == 0){
        float ts = 0.f, cs = 0.f;
#pragma unroll
        for (int w = 0; w < 8; ++w){ ts += s_red[w]; cs += s_red[8 + w]; }
        atomicAdd(&g_acc[1], (double)ts);
        atomicAdd(&g_acc[2], (double)cs);
    }
}

__global__ void k_final(float* out, int n){
    double v = g_acc[0] / (double)NROWS + 0.1 * (g_acc[1] - 2.0 * g_acc[2]);
    for (int i = threadIdx.x; i < n; i += blockDim.x) out[i] = (float)v;
}

extern "C" void kernel_launch(void* const* d_in, const int* in_sizes, int n_in,
                              void* d_out, int out_size){
    const float* preds = (const float*)d_in[0];
    const int*   tgt   = (const int*)d_in[1];
    const float* L     = (const float*)d_in[2];
    const float* X     = (const float*)d_in[3];
    float* out = (float*)d_out;
    (void)in_sizes; (void)n_in;

    cudaFuncSetAttribute((const void*)k_main, cudaFuncAttributeMaxDynamicSharedMemorySize, DYN_BYTES);

    k_prep<<<NROWS/64, 256>>>(X);
    k_main<<<148, 256, DYN_BYTES>>>(L, X, preds, tgt);
    k_final<<<1, 256>>>(out, out_size);
}

// round 9
// speedup vs baseline: 1.1478x; 1.0043x over previous
#include <cuda_runtime.h>
#include <cstdint>

#define NROWS 8192
#define DDIM  128
#define NCLS  1000
#define KSPLIT 4
#define KRANGE (NROWS/KSPLIT)  // 2048
#define KCH   32
#define NCHUNK (KRANGE/KCH)    // 64
#define NSTAGE 3
#define APAD  36               // floats per smem row (32 + 4 pad) -> conflict-free frags
#define TILE_B (128*APAD*4)    // 18432 B per stage per operand
#define OFF_B   (NSTAGE*TILE_B)       // 55296
#define DYN_BYTES (2*NSTAGE*TILE_B)   // 110592
#define NGEMM 256              // GEMM CTAs (64 mtiles x 4 ksplits)
#define NCE   20

__device__ __align__(16) float g_XT[(size_t)DDIM*NROWS];  // tf32-rounded X^T [d][j]
__device__ float  g_sq[NROWS];
__device__ double g_acc[3];   // 0: ce-sum  1: T  2: cross

// ---------------- helpers ----------------
__device__ __forceinline__ uint32_t smem_u32(const void* p){
    uint32_t a;
    asm("{ .reg .u64 t; cvta.to.shared.u64 t, %1; cvt.u32.u64 %0, t; }" : "=r"(a) : "l"(p));
    return a;
}
__device__ __forceinline__ uint32_t f2tf32(float x){
    uint32_t u;
    asm("cvt.rna.tf32.f32 %0, %1;" : "=r"(u) : "f"(x));
    return u;
}
__device__ __forceinline__ uint32_t lds32(uint32_t a){
    uint32_t v;
    asm("ld.shared.b32 %0, [%1];" : "=r"(v) : "r"(a));
    return v;
}
__device__ __forceinline__ float4 lds128f(uint32_t a){
    float4 v;
    asm volatile("ld.shared.v4.f32 {%0,%1,%2,%3}, [%4];"
                 : "=f"(v.x), "=f"(v.y), "=f"(v.z), "=f"(v.w) : "r"(a));
    return v;
}
__device__ __forceinline__ void cp16(uint32_t dst, const void* src){
    asm volatile("cp.async.cg.shared.global [%0], [%1], 16;" :: "r"(dst), "l"(src));
}
__device__ __forceinline__ void mma_tf32(float* c, const uint32_t* a, const uint32_t* b){
    asm volatile(
        "mma.sync.aligned.m16n8k8.row.col.f32.tf32.tf32.f32 "
        "{%0,%1,%2,%3}, {%4,%5,%6,%7}, {%8,%9}, {%0,%1,%2,%3};"
        : "+f"(c[0]), "+f"(c[1]), "+f"(c[2]), "+f"(c[3])
        : "r"(a[0]), "r"(a[1]), "r"(a[2]), "r"(a[3]), "r"(b[0]), "r"(b[1]));
}

// ---------------- prep: zero acc, sq[j] exact, XT tf32 ----------------
__global__ void __launch_bounds__(256) k_prep(const float* __restrict__ X){
    __shared__ float tile[64*129];
    int tid = threadIdx.x;
    int j0 = blockIdx.x * 64;
    if (blockIdx.x == 0 && tid < 3) g_acc[tid] = 0.0;
#pragma unroll
    for (int p = 0; p < 8; ++p){
        int idx = p*256 + tid;
        int r = idx >> 5;
        int c = idx & 31;
        float4 v = ((const float4*)(X + (size_t)(j0 + r)*DDIM))[c];
        tile[r*129 + c*4 + 0] = v.x;
        tile[r*129 + c*4 + 1] = v.y;
        tile[r*129 + c*4 + 2] = v.z;
        tile[r*129 + c*4 + 3] = v.w;
    }
    __syncthreads();
    if (tid < 64){
        float s = 0.f;
        const float* row = tile + tid*129;
#pragma unroll 8
        for (int c = 0; c < 128; ++c) s += row[c]*row[c];
        g_sq[j0 + tid] = s;
    }
#pragma unroll
    for (int p = 0; p < 8; ++p){
        int u  = p*256 + tid;
        int d  = u >> 4;
        int ju = (u & 15) * 4;
        uint4 o;
        o.x = f2tf32(tile[(ju+0)*129 + d]);
        o.y = f2tf32(tile[(ju+1)*129 + d]);
        o.z = f2tf32(tile[(ju+2)*129 + d]);
        o.w = f2tf32(tile[(ju+3)*129 + d]);
        *(uint4*)(g_XT + (size_t)d*NROWS + j0 + ju) = o;
    }
}

// ---------------- main: GEMM blocks 0..255, CE blocks 256..275 ----------------
__global__ void __launch_bounds__(256, 2)
k_main(const float* __restrict__ L, const float* __restrict__ X,
       const float* __restrict__ preds, const int* __restrict__ tgt){
    extern __shared__ __align__(16) char dyn[];
    __shared__ float s_red[16];
    int tid = threadIdx.x, wid = tid>>5, lane = tid&31;

    if (blockIdx.x >= NGEMM){
        // ---- cross-entropy: 20 CTAs x 8 warps ----
        int g = (blockIdx.x - NGEMM)*8 + wid;     // 0..159
        float ce = 0.f;
        for (int r = g; r < NROWS; r += NCE*8){
            const float4* row4 = (const float4*)(preds + (size_t)r*NCLS);
            float s = 0.f;
            for (int c4 = lane; c4 < NCLS/4; c4 += 32){
                float4 v = __ldg(row4 + c4);
                s += __expf(v.x) + __expf(v.y) + __expf(v.z) + __expf(v.w);
            }
#pragma unroll
            for (int o = 16; o; o >>= 1) s += __shfl_xor_sync(~0u, s, o);
            if (lane == 0)
                ce += __logf(s) - __ldg(preds + (size_t)r*NCLS + __ldg(tgt + r));
        }
        if (lane == 0) atomicAdd(&g_acc[0], (double)ce);
        return;
    }

    // ---- GEMM + fused T ----
    uint32_t base = smem_u32(dyn);
    int m0 = (blockIdx.x >> 2) * 128;
    int k0 = (blockIdx.x & 3) * KRANGE;

    int lrow = tid >> 1, lhalf = tid & 1;
    const float* Ap  = L    + (size_t)(m0 + lrow)*NROWS + k0 + lhalf*16;
    const float* Bp  = g_XT + (size_t)lrow*NROWS       + k0 + lhalf*16;
    const float* sqp = g_sq + k0 + lhalf*16;
    float my_sqm = __ldg(g_sq + m0 + lrow);
    uint32_t aoff = (uint32_t)(lrow*APAD + lhalf*16)*4;

    // prologue: stages 0..NSTAGE-2
#pragma unroll
    for (int s = 0; s < NSTAGE-1; ++s){
        uint32_t da = base + s*TILE_B + aoff;
        uint32_t db = da + OFF_B;
#pragma unroll
        for (int q = 0; q < 4; ++q){
            cp16(da + q*16, Ap + s*KCH + q*4);
            cp16(db + q*16, Bp + s*KCH + q*4);
        }
        asm volatile("cp.async.commit_group;" ::: "memory");
    }

    int warp_m = wid >> 2, warp_n = wid & 3;
    int r = lane >> 2, cg = lane & 3;
    uint32_t aA = base + (uint32_t)((warp_m*64 + r)*APAD + cg)*4;
    uint32_t aB = base + OFF_B + (uint32_t)((warp_n*32 + r)*APAD + cg)*4;

    float acc[4][4][4];
#pragma unroll
    for (int i = 0; i < 4; ++i)
#pragma unroll
        for (int j = 0; j < 4; ++j)
#pragma unroll
            for (int q = 0; q < 4; ++q) acc[i][j][q] = 0.f;
    float tloc = 0.f;

#pragma unroll 1
    for (int c = 0; c < NCHUNK; ++c){
        asm volatile("cp.async.wait_group %0;" :: "n"(NSTAGE-2) : "memory");
        __syncthreads();

        // stage c+NSTAGE-1 (buf (c-1)%NSTAGE, fully consumed before this barrier)
        int cn = c + NSTAGE - 1;
        if (cn < NCHUNK){
            int bufn = cn % NSTAGE;
            uint32_t da = base + bufn*TILE_B + aoff;
            uint32_t db = da + OFF_B;
#pragma unroll
            for (int q = 0; q < 4; ++q){
                cp16(da + q*16, Ap + cn*KCH + q*4);
                cp16(db + q*16, Bp + cn*KCH + q*4);
            }
        }
        asm volatile("cp.async.commit_group;" ::: "memory");

        int buf = c % NSTAGE;

        // fused T: read back this thread's raw L values from smem; sq via LDG (L1/L2-hot)
        {
            uint32_t ta = base + buf*TILE_B + aoff;
#pragma unroll
            for (int q = 0; q < 4; ++q){
                float4 v = lds128f(ta + q*16);
                float4 s4 = __ldg((const float4*)(sqp + c*KCH) + q);
                tloc += (v.x+v.y+v.z+v.w)*my_sqm
                      + v.x*s4.x + v.y*s4.y + v.z*s4.z + v.w*s4.w;
            }
        }

        // MMA over buffer c (A = raw fp32 bits, HW truncates to tf32)
        uint32_t bA = aA + buf*TILE_B;
        uint32_t bB = aB + buf*TILE_B;
#pragma unroll
        for (int k8 = 0; k8 < KCH; k8 += 8){
            uint32_t af[4][4], bf[4][2];
#pragma unroll
            for (int tm = 0; tm < 4; ++tm){
                uint32_t p = bA + (uint32_t)(tm*16*APAD + k8)*4;
                af[tm][0] = lds32(p);
                af[tm][1] = lds32(p + 8*APAD*4);
                af[tm][2] = lds32(p + 16);
                af[tm][3] = lds32(p + 8*APAD*4 + 16);
            }
#pragma unroll
            for (int tn = 0; tn < 4; ++tn){
                uint32_t p = bB + (uint32_t)(tn*8*APAD + k8)*4;
                bf[tn][0] = lds32(p);
                bf[tn][1] = lds32(p + 16);
            }
#pragma unroll
            for (int tm = 0; tm < 4; ++tm)
#pragma unroll
                for (int tn = 0; tn < 4; ++tn)
                    mma_tf32(acc[tm][tn], af[tm], bf[tn]);
        }
    }

    // epilogue: cross += acc .* X (exact fp32)
    float cpart = 0.f;
#pragma unroll
    for (int tm = 0; tm < 4; ++tm){
#pragma unroll
        for (int tn = 0; tn < 4; ++tn){
#pragma unroll
            for (int q = 0; q < 4; ++q){
                int mrow = m0 + warp_m*64 + tm*16 + r + ((q>>1)<<3);
                int ncol = warp_n*32 + tn*8 + cg*2 + (q&1);
                cpart += acc[tm][tn][q] * __ldg(X + (size_t)mrow*DDIM + ncol);
            }
        }
    }

#pragma unroll
    for (int o = 16; o; o >>= 1){
        tloc  += __shfl_xor_sync(~0u, tloc,  o);
        cpart += __shfl_xor_sync(~0u, cpart, o);
    }
    if (lane == 0){ s_red[wid] = tloc; s_red[8 + wid] = cpart; }
    __syncthreads();
    if (tid == 0){
        float ts = 0.f, cs = 0.f;
#pragma unroll
        for (int w = 0; w < 8; ++w){ ts += s_red[w]; cs += s_red[8 + w]; }
        atomicAdd(&g_acc[1], (double)ts);
        atomicAdd(&g_acc[2], (double)cs);
    }
}

__global__ void k_final(float* out, int n){
    double v = g_acc[0] / (double)NROWS + 0.1 * (g_acc[1] - 2.0 * g_acc[2]);
    for (int i = threadIdx.x; i < n; i += blockDim.x) out[i] = (float)v;
}

extern "C" void kernel_launch(void* const* d_in, const int* in_sizes, int n_in,
                              void* d_out, int out_size){
    const float* preds = (const float*)d_in[0];
    const int*   tgt   = (const int*)d_in[1];
    const float* L     = (const float*)d_in[2];
    const float* X     = (const float*)d_in[3];
    float* out = (float*)d_out;
    (void)in_sizes; (void)n_in;

    cudaFuncSetAttribute((const void*)k_main, cudaFuncAttributeMaxDynamicSharedMemorySize, DYN_BYTES);

    k_prep<<<NROWS/64, 256>>>(X);
    k_main<<<NGEMM + NCE, 256, DYN_BYTES>>>(L, X, preds, tgt);
    k_final<<<1, 256>>>(out, out_size);
}